// round 12
// baseline (speedup 1.0000x reference)
#include <cuda_runtime.h>
#include <cuda_bf16.h>

#define NB 8
#define NI 64
#define NO 64
#define NN 8192
#define NK 16
#define ND 3
#define NH1 16
#define NH2 32
#define TN 8
#define ROWS 128
#define NTHREADS 256
#define BON (NB*NO*NN)
#define SPN (NB*ND*NN)
#define CSTRIDE (NN*NK)      // 131072: element stride between i-channels of input

typedef unsigned long long u64;
typedef unsigned int u32;

// ---- smem: H scratch + small arrays only (B frags now global) ----
#define SM_SCR   0            // H scratch fp32 [row:128][42 words padded] = 21504 B
#define SM_SMALL 21504
#define SMEM_BYTES (SM_SMALL + 1248*4)
#define SCR_PAD 42

// ---- global fragment buffers (built once per launch by prep kernel) ----
// g_bf[(nt*4+s)*32 + lane]  = {bh0, bh1, bl0, bl1} for weight (GEMM1)
// g_b2f[(nt*2+s)*32 + lane] = same for W3 (GEMM2)
__device__ uint4 g_bf[32*32];
__device__ uint4 g_b2f[16*32];

__device__ __forceinline__ u64 pack2(float x, float y) {
    u64 r; asm("mov.b64 %0,{%1,%2};" : "=l"(r) : "f"(x), "f"(y)); return r;
}
__device__ __forceinline__ u64 fma2(u64 a, u64 b, u64 c) {
    u64 d; asm("fma.rn.f32x2 %0,%1,%2,%3;" : "=l"(d) : "l"(a), "l"(b), "l"(c)); return d;
}
__device__ __forceinline__ float2 unpack2(u64 v) {
    float2 f; asm("mov.b64 {%0,%1},%2;" : "=f"(f.x), "=f"(f.y) : "l"(v)); return f;
}
__device__ __forceinline__ u32 bf2bits(__nv_bfloat162 h) { return *reinterpret_cast<u32*>(&h); }

__device__ __forceinline__ void split_pair(float f0, float f1, u32& hi, u32& lo) {
    __nv_bfloat162 hb = __float22bfloat162_rn(make_float2(f0, f1));
    float2 hf = __bfloat1622float2(hb);
    __nv_bfloat162 lb = __float22bfloat162_rn(make_float2(f0 - hf.x, f1 - hf.y));
    hi = bf2bits(hb); lo = bf2bits(lb);
}

#define MMA16816(c, a, b) \
    asm volatile("mma.sync.aligned.m16n8k16.row.col.f32.bf16.bf16.f32 " \
        "{%0,%1,%2,%3}, {%4,%5,%6,%7}, {%8,%9}, {%0,%1,%2,%3};" \
        : "+f"((c)[0]), "+f"((c)[1]), "+f"((c)[2]), "+f"((c)[3]) \
        : "r"((a).x), "r"((a).y), "r"((a).z), "r"((a).w), \
          "r"((b).x), "r"((b).y))

// ================= prep kernel: build B fragments once =================
__global__ void pccn_prep(const float* __restrict__ weight, const float* __restrict__ W3)
{
    const int tid  = threadIdx.x;
    const int lane = tid & 31;
    const int gid  = lane >> 2;
    const int tig  = lane & 3;
    for (int blk = tid >> 5; blk < 32; blk += 8) {
        int nt = blk >> 2, s = blk & 3;
        int n = 8*nt + gid, k0 = 16*s + 2*tig;
        float w00 = weight[k0*NO + n],     w01 = weight[(k0+1)*NO + n];
        float w10 = weight[(k0+8)*NO + n], w11 = weight[(k0+9)*NO + n];
        u32 h0,l0,h1,l1;
        split_pair(w00, w01, h0, l0);
        split_pair(w10, w11, h1, l1);
        g_bf[blk*32 + lane] = make_uint4(h0, h1, l0, l1);
    }
    for (int blk = tid >> 5; blk < 16; blk += 8) {
        int nt = blk >> 1, s = blk & 1;
        int n = 8*nt + gid, k0 = 16*s + 2*tig;
        float w00 = W3[k0*NO + n],     w01 = W3[(k0+1)*NO + n];
        float w10 = W3[(k0+8)*NO + n], w11 = W3[(k0+9)*NO + n];
        u32 h0,l0,h1,l1;
        split_pair(w00, w01, h0, l0);
        split_pair(w10, w11, h1, l1);
        g_b2f[blk*32 + lane] = make_uint4(h0, h1, l0, l1);
    }
}

__global__ void __launch_bounds__(NTHREADS, 2)
pccn_kernel(const float* __restrict__ input, const float* __restrict__ points,
            const float* __restrict__ support, const float* __restrict__ bias,
            const float* __restrict__ W1, const float* __restrict__ b1,
            const float* __restrict__ W2, const float* __restrict__ b2,
            const float* __restrict__ b3, float* __restrict__ out, int copy_sp)
{
    extern __shared__ char smemc[];
    float* scr = (float*)(smemc + SM_SCR);
    float* sW1   = (float*)(smemc + SM_SMALL);
    float* sb1   = sW1 + 48;
    float* sW2   = sb1 + 16;
    float* sb2   = sW2 + 512;
    float* sb3   = sb2 + 32;
    float* sBias = sb3 + 64;
    float* sOut  = sBias + 64;        // [n_local:8][o:64]

    const int tid  = threadIdx.x;
    const int warp = tid >> 5;
    const int lane = tid & 31;
    const int gid  = lane >> 2;
    const int tig  = lane & 3;
    const int blk  = blockIdx.x;
    const int b    = blk >> 10;
    const int n0   = (blk & 1023) * TN;

    // ---- small arrays ----
    for (int idx = tid; idx < NH1*NH2; idx += NTHREADS) sW2[idx] = W2[idx];
    if (tid < 48) sW1[tid]  = W1[tid];
    if (tid < 16) sb1[tid]  = b1[tid];
    if (tid < 32) sb2[tid]  = b2[tid];
    if (tid < 64) sb3[tid]  = b3[tid];
    if (tid < 64) sBias[tid] = bias[tid];

    // ========== X direct loads: warp w reads its own 16 rows (8 floats/lane/s) ==========
    float xr[32];
    {
        const float* base = input + (size_t)b*NI*CSTRIDE + (size_t)n0*NK;
        const int r0 = 16*warp + gid;
#pragma unroll
        for (int s = 0; s < 4; s++) {
            const float* pc = base + (size_t)(16*s + 2*tig)*CSTRIDE;
            xr[s*8+0] = pc[r0];
            xr[s*8+1] = pc[CSTRIDE + r0];
            xr[s*8+2] = pc[r0 + 8];
            xr[s*8+3] = pc[CSTRIDE + r0 + 8];
            xr[s*8+4] = pc[8*CSTRIDE + r0];
            xr[s*8+5] = pc[9*CSTRIDE + r0];
            xr[s*8+6] = pc[8*CSTRIDE + r0 + 8];
            xr[s*8+7] = pc[9*CSTRIDE + r0 + 8];
        }
    }

    __syncthreads();   // small arrays ready

    // ========== coords + MLP -> fp32 scratch (threads 0..127, row = tid) ==========
    if (tid < ROWS) {
        const int row = tid;
        const int k = row & 15;
        const int n = n0 + (row >> 4);
        float p0 = points[(((size_t)b*ND + 0)*NN + n)*NK + k] - support[((size_t)b*ND + 0)*NN + n];
        float p1 = points[(((size_t)b*ND + 1)*NN + n)*NK + k] - support[((size_t)b*ND + 1)*NN + n];
        float p2 = points[(((size_t)b*ND + 2)*NN + n)*NK + k] - support[((size_t)b*ND + 2)*NN + n];
        float sq = p0*p0 + p1*p1 + p2*p2;
        float m = sq;
#pragma unroll
        for (int off = 8; off > 0; off >>= 1)
            m = fmaxf(m, __shfl_xor_sync(0xffffffffu, m, off));
        float maxi = sqrtf(m);
        maxi += (maxi == 0.0f) ? 1.0f : 0.0f;
        float inv = 1.0f / maxi;
        float x0 = p0*inv, x1 = p1*inv, x2 = p2*inv;

        float h1[NH1];
#pragma unroll
        for (int a = 0; a < NH1; a++) {
            float v = sb1[a] + x0*sW1[a] + x1*sW1[16 + a] + x2*sW1[32 + a];
            h1[a] = fmaxf(v, 0.0f);
        }
        u64 h2p[NH2/2];
#pragma unroll
        for (int jp = 0; jp < NH2/2; jp++) h2p[jp] = ((const u64*)sb2)[jp];
#pragma unroll
        for (int a = 0; a < NH1; a++) {
            u64 xd = pack2(h1[a], h1[a]);
            const u64* wrow = (const u64*)(sW2 + a*NH2);
#pragma unroll
            for (int jp = 0; jp < NH2/2; jp++) h2p[jp] = fma2(xd, wrow[jp], h2p[jp]);
        }
#pragma unroll
        for (int jp = 0; jp < 16; jp++) {
            float2 v = unpack2(h2p[jp]);
            v.x = fmaxf(v.x, 0.0f); v.y = fmaxf(v.y, 0.0f);
            *(float2*)(scr + row*SCR_PAD + 2*jp) = v;
        }
    }

    __syncthreads();

    // ========== GEMMs via mma.sync (warp w -> rows 16w..16w+15 = n_local w) ==========
    float c1[8][4], c2[8][4];
#pragma unroll
    for (int nt = 0; nt < 8; nt++)
#pragma unroll
        for (int r = 0; r < 4; r++) { c1[nt][r] = 0.0f; c2[nt][r] = 0.0f; }

    // GEMM1: C1 = X @ W (K=64), A from registers, B frags direct from global (L1-hit)
#pragma unroll
    for (int s = 0; s < 4; s++) {
        uint4 ah, al;
        split_pair(xr[s*8+0], xr[s*8+1], ah.x, al.x);
        split_pair(xr[s*8+2], xr[s*8+3], ah.y, al.y);
        split_pair(xr[s*8+4], xr[s*8+5], ah.z, al.z);
        split_pair(xr[s*8+6], xr[s*8+7], ah.w, al.w);
#pragma unroll
        for (int nt = 0; nt < 8; nt++) {
            uint4 bb = __ldg(&g_bf[(nt*4 + s)*32 + lane]);
            uint2 bh = make_uint2(bb.x, bb.y);
            uint2 bl = make_uint2(bb.z, bb.w);
            MMA16816(c1[nt], ah, bh);
            MMA16816(c1[nt], ah, bl);
            MMA16816(c1[nt], al, bh);
        }
    }
    // GEMM2: C2 = H @ W3 (K=32), A from scratch, B frags direct from global
#pragma unroll
    for (int s = 0; s < 2; s++) {
        const int c0 = 16*s + 2*tig;
        const int r0 = 16*warp + gid;
        float2 p00 = *(const float2*)(scr + r0*SCR_PAD + c0);
        float2 p10 = *(const float2*)(scr + (r0+8)*SCR_PAD + c0);
        float2 p01 = *(const float2*)(scr + r0*SCR_PAD + c0 + 8);
        float2 p11 = *(const float2*)(scr + (r0+8)*SCR_PAD + c0 + 8);
        uint4 ah, al;
        split_pair(p00.x, p00.y, ah.x, al.x);
        split_pair(p10.x, p10.y, ah.y, al.y);
        split_pair(p01.x, p01.y, ah.z, al.z);
        split_pair(p11.x, p11.y, ah.w, al.w);
#pragma unroll
        for (int nt = 0; nt < 8; nt++) {
            uint4 bb = __ldg(&g_b2f[(nt*2 + s)*32 + lane]);
            uint2 bh = make_uint2(bb.x, bb.y);
            uint2 bl = make_uint2(bb.z, bb.w);
            MMA16816(c2[nt], ah, bh);
            MMA16816(c2[nt], ah, bl);
            MMA16816(c2[nt], al, bh);
        }
    }

    // ========== combine: out[n,o] = sum_rows C1 * (C2 + b3) ==========
    {
#pragma unroll
        for (int nt = 0; nt < 8; nt++) {
            float b3e = sb3[8*nt + 2*tig];
            float b3o = sb3[8*nt + 2*tig + 1];
            float s0 = c1[nt][0]*(c2[nt][0] + b3e) + c1[nt][2]*(c2[nt][2] + b3e);
            float s1 = c1[nt][1]*(c2[nt][1] + b3o) + c1[nt][3]*(c2[nt][3] + b3o);
#pragma unroll
            for (int msk = 4; msk <= 16; msk <<= 1) {
                s0 += __shfl_xor_sync(0xffffffffu, s0, msk);
                s1 += __shfl_xor_sync(0xffffffffu, s1, msk);
            }
            if (lane < 4) {
                sOut[warp*NO + 8*nt + 2*tig]     = s0;
                sOut[warp*NO + 8*nt + 2*tig + 1] = s1;
            }
        }
    }

    __syncthreads();

    // ========== epilogue: out (B, O, N) + bias ==========
    if (tid < 128) {
        int o = tid >> 1, half = tid & 1;
        float4 rr;
        rr.x = sOut[(half*4+0)*NO + o] + sBias[o];
        rr.y = sOut[(half*4+1)*NO + o] + sBias[o];
        rr.z = sOut[(half*4+2)*NO + o] + sBias[o];
        rr.w = sOut[(half*4+3)*NO + o] + sBias[o];
        *(float4*)(out + ((size_t)b*NO + o)*NN + n0 + half*4) = rr;
    }

    // ---- support_points passthrough ----
    if (copy_sp) {
        for (int idx = blk*NTHREADS + tid; idx < SPN; idx += gridDim.x*NTHREADS)
            out[BON + idx] = support[idx];
    }
}

extern "C" void kernel_launch(void* const* d_in, const int* in_sizes, int n_in,
                              void* d_out, int out_size) {
    const float* input   = (const float*)d_in[0];
    const float* points  = (const float*)d_in[1];
    const float* support = (const float*)d_in[2];
    const float* weight  = (const float*)d_in[3];
    const float* bias    = (const float*)d_in[4];
    const float* W1      = (const float*)d_in[5];
    const float* b1      = (const float*)d_in[6];
    const float* W2      = (const float*)d_in[7];
    const float* b2      = (const float*)d_in[8];
    const float* W3      = (const float*)d_in[9];
    const float* b3      = (const float*)d_in[10];

    int copy_sp = (out_size > BON) ? 1 : 0;
    pccn_prep<<<1, NTHREADS>>>(weight, W3);
    pccn_kernel<<<NB*(NN/TN), NTHREADS, SMEM_BYTES>>>(
        input, points, support, bias, W1, b1, W2, b2, b3,
        (float*)d_out, copy_sp);
}